// round 16
// baseline (speedup 1.0000x reference)
#include <cuda_runtime.h>
#include <cuda_fp16.h>
#include <cstdint>

// Problem constants (fixed by the dataset)
#define NN 100000
#define EE 1600000
#define FF 128
#define GG 64
#define CC 3

#define SB 1024
#define NSB ((NN + SB - 1) / SB)   // 98

// Scratch: __device__ globals (no allocation allowed)
__device__ int    g_deg[NN];
__device__ float  g_dis[NN];
__device__ __half g_h1h[(size_t)NN * FF];  // GEMM output (fp16; gather consumes)
__device__ __half g_aggh[(size_t)NN * FF]; // activated aggregation (fp16; GEMM consumes)
__device__ float  g_sums[GG * FF];
__device__ float  g_cnt[GG];
__device__ int    g_rowoff[NN];
__device__ int    g_cursor[NN];
__device__ int    g_bsum[NSB];
__device__ int2   g_csr[EE];               // interleaved {src, coef_bits}
// Pre-transposed, hi/lo-split weights: Wt[n][k] fp16 (W = Wh + Wl exactly-ish)
__device__ __align__(16) __half g_wt_h[3][FF * FF];
__device__ __align__(16) __half g_wt_l[3][FF * FF];

__device__ __forceinline__ void red_add_v4(float* addr, float x, float y, float z, float w) {
    asm volatile("red.global.add.v4.f32 [%0], {%1, %2, %3, %4};"
                 :: "l"(addr), "f"(x), "f"(y), "f"(z), "f"(w) : "memory");
}

__device__ __forceinline__ void mma16816(float* c, const uint32_t* a, uint32_t b0, uint32_t b1) {
    asm volatile(
        "mma.sync.aligned.m16n8k16.row.col.f32.f16.f16.f32 "
        "{%0,%1,%2,%3}, {%4,%5,%6,%7}, {%8,%9}, {%0,%1,%2,%3};\n"
        : "+f"(c[0]), "+f"(c[1]), "+f"(c[2]), "+f"(c[3])
        : "r"(a[0]), "r"(a[1]), "r"(a[2]), "r"(a[3]), "r"(b0), "r"(b1));
}

// ---------------- init / degree ----------------

__global__ void k_init() {
    int i = blockIdx.x * blockDim.x + threadIdx.x;
    if (i < NN) g_deg[i] = 1;             // self-loop
    if (i < GG * FF) g_sums[i] = 0.0f;
    if (i < GG) g_cnt[i] = 0.0f;
}

// 4 edges per thread (int4 index loads)
__global__ void k_count(const int* __restrict__ dst) {
    int q = blockIdx.x * blockDim.x + threadIdx.x;   // quad index
    if (q * 4 >= EE) return;
    int4 d4 = *(const int4*)(dst + q * 4);
    atomicAdd(&g_deg[d4.x], 1);
    atomicAdd(&g_deg[d4.y], 1);
    atomicAdd(&g_deg[d4.z], 1);
    atomicAdd(&g_deg[d4.w], 1);
}

// ---------------- weight prep: Wt_h/Wt_l[n][k] = hi/lo fp16 split of W[k][n] ----------

__global__ void k_wprep(const float* __restrict__ W1, const float* __restrict__ W2,
                        const float* __restrict__ W3) {
    int idx = blockIdx.x * blockDim.x + threadIdx.x;
    if (idx >= 3 * FF * FF) return;
    int mat = idx / (FF * FF);
    int r   = idx % (FF * FF);
    int n = r / FF, k = r % FF;
    const float* W = (mat == 0) ? W1 : (mat == 1) ? W2 : W3;
    float w = W[k * FF + n];
    __half h = __float2half_rn(w);
    __half l = __float2half_rn(w - __half2float(h));
    g_wt_h[mat][n * FF + k] = h;
    g_wt_l[mat][n * FF + k] = l;
}

// ---------------- fused: dis/cursor/graph-count + per-block degree sums ----------------

__global__ __launch_bounds__(SB) void k_bsum(const int* __restrict__ batch) {
    __shared__ int sh[SB];
    int i = blockIdx.x * SB + threadIdx.x;
    int d = 0;
    if (i < NN) {
        d = g_deg[i];
        g_dis[i] = rsqrtf((float)d);
        g_cursor[i] = 0;
        atomicAdd(&g_cnt[batch[i]], 1.0f);
    }
    sh[threadIdx.x] = (i < NN) ? (d - 1) : 0;
    __syncthreads();
    for (int s = SB / 2; s > 0; s >>= 1) {
        if (threadIdx.x < s) sh[threadIdx.x] += sh[threadIdx.x + s];
        __syncthreads();
    }
    if (threadIdx.x == 0) g_bsum[blockIdx.x] = sh[0];
}

// rowoff with fused inter-block scan: each block computes its own base as a
// masked block-reduce over g_bsum (removes the separate scan launch).
__global__ __launch_bounds__(SB) void k_rowoff() {
    __shared__ int sh[SB];
    __shared__ int bs[128];
    int t = threadIdx.x;

    if (t < 128) bs[t] = (t < NSB && t < blockIdx.x) ? g_bsum[t] : 0;
    __syncthreads();
    for (int s = 64; s > 0; s >>= 1) {
        if (t < s) bs[t] += bs[t + s];
        __syncthreads();
    }
    int base = bs[0];

    int i = blockIdx.x * SB + t;
    int v = (i < NN) ? (g_deg[i] - 1) : 0;
    sh[t] = v;
    __syncthreads();
    for (int off = 1; off < SB; off <<= 1) {
        int u = (t >= off) ? sh[t - off] : 0;
        __syncthreads();
        sh[t] += u;
        __syncthreads();
    }
    if (i < NN)
        g_rowoff[i] = base + sh[t] - v;   // exclusive
}

// 4 edges per thread (int4 index loads)
__global__ void k_bin(const int* __restrict__ src, const int* __restrict__ dst) {
    int q = blockIdx.x * blockDim.x + threadIdx.x;
    if (q * 4 >= EE) return;
    int4 s4 = *(const int4*)(src + q * 4);
    int4 d4 = *(const int4*)(dst + q * 4);
#pragma unroll
    for (int u = 0; u < 4; u++) {
        int s = (u == 0) ? s4.x : (u == 1) ? s4.y : (u == 2) ? s4.z : s4.w;
        int d = (u == 0) ? d4.x : (u == 1) ? d4.y : (u == 2) ? d4.z : d4.w;
        int pos = atomicAdd(&g_cursor[d], 1);
        int idx = g_rowoff[d] + pos;
        float coef = g_dis[s] * g_dis[d];
        g_csr[idx] = make_int2(s, __float_as_int(coef));
    }
}

// ---------------- HMMA GEMM: h1h = fp16( A @ W ) ----------------
// Two-pass over a single B buffer (Wh then Wl, same fp32 accumulators):
// SMEM 102KB -> 68KB => 3 blocks/SM, so load phases overlap other blocks' MMA.
// A is external fp32 x (layer 1) or fp16 g_aggh (layers 2/3, pre-activated).
// mma.sync.m16n8k16, 8 warps in 4x2 grid, padded SMEM rows (APAD=136 halves).

#define APAD 136
#define SM_A  0                      // halves offsets
#define SM_B  (128 * APAD)
#define SM_BYTES (256 * APAD * 2)    // 69632

__global__ __launch_bounds__(256) void k_gemm(
    const float* __restrict__ Aext, int useAgg, int wmat, int nrows)
{
    extern __shared__ __half sh[];
    int block_row = blockIdx.x * 128;
    int tid = threadIdx.x;

    // ---- load A tile into SMEM as fp16 ----
    if (useAgg) {
#pragma unroll
        for (int it = 0; it < 8; it++) {
            int q = tid + it * 256;      // 2048 uint4
            int row = q >> 4;
            int col = (q & 15) * 8;
            int grow = block_row + row;
            uint4 v = make_uint4(0u, 0u, 0u, 0u);
            if (grow < nrows) v = *(const uint4*)(g_aggh + (size_t)grow * FF + col);
            *(uint4*)(sh + SM_A + row * APAD + col) = v;
        }
    } else {
#pragma unroll
        for (int it = 0; it < 16; it++) {
            int q = tid + it * 256;      // 4096 float4
            int row = q >> 5;
            int col = (q & 31) * 4;
            int grow = block_row + row;
            float4 av = make_float4(0.f, 0.f, 0.f, 0.f);
            if (grow < nrows) av = *(const float4*)(Aext + (size_t)grow * FF + col);
            __half2 p0 = __floats2half2_rn(av.x, av.y);
            __half2 p1 = __floats2half2_rn(av.z, av.w);
            uint2 packed = make_uint2(*(uint32_t*)&p0, *(uint32_t*)&p1);
            *(uint2*)(sh + SM_A + row * APAD + col) = packed;
        }
    }

    int wid = tid >> 5, lane = tid & 31;
    int wm = wid >> 1, wn = wid & 1;     // 4x2 warp grid: 32 rows x 64 cols each
    int g = lane >> 2, t4 = lane & 3;

    float c[2][8][4];
#pragma unroll
    for (int mt = 0; mt < 2; mt++)
#pragma unroll
        for (int nt = 0; nt < 8; nt++)
#pragma unroll
            for (int r = 0; r < 4; r++) c[mt][nt][r] = 0.0f;

    for (int pass = 0; pass < 2; pass++) {
        // copy Wt (hi on pass 0, lo on pass 1) into SMEM B buffer
        const uint4* wsrc = pass ? (const uint4*)&g_wt_l[wmat][0]
                                 : (const uint4*)&g_wt_h[wmat][0];
#pragma unroll
        for (int it = 0; it < 8; it++) {
            int q = tid + it * 256;      // 2048 uint4
            int n = q >> 4;
            int k = (q & 15) * 8;
            *(uint4*)(sh + SM_B + n * APAD + k) = wsrc[q];
        }
        __syncthreads();

        for (int ks = 0; ks < 8; ks++) {
            int kb = ks * 16;
            uint32_t a[2][4];
#pragma unroll
            for (int mt = 0; mt < 2; mt++) {
                const __half* ab = sh + SM_A + (wm * 32 + mt * 16 + g) * APAD + kb + 2 * t4;
                a[mt][0] = *(const uint32_t*)(ab);
                a[mt][1] = *(const uint32_t*)(ab + 8 * APAD);
                a[mt][2] = *(const uint32_t*)(ab + 8);
                a[mt][3] = *(const uint32_t*)(ab + 8 * APAD + 8);
            }
#pragma unroll
            for (int nt = 0; nt < 8; nt++) {
                int coff = (wn * 64 + nt * 8 + g) * APAD + kb + 2 * t4;
                uint32_t b0 = *(const uint32_t*)(sh + SM_B + coff);
                uint32_t b1 = *(const uint32_t*)(sh + SM_B + coff + 8);
                mma16816(c[0][nt], a[0], b0, b1);
                mma16816(c[1][nt], a[1], b0, b1);
            }
        }
        __syncthreads();   // mainloop reads done before next pass overwrites B
    }

    // ---- epilogue: fp16 store ----
#pragma unroll
    for (int mt = 0; mt < 2; mt++) {
        int r0 = block_row + wm * 32 + mt * 16 + g;
#pragma unroll
        for (int nt = 0; nt < 8; nt++) {
            int col = wn * 64 + nt * 8 + 2 * t4;
            __half2 lo = __floats2half2_rn(c[mt][nt][0], c[mt][nt][1]);
            __half2 hi = __floats2half2_rn(c[mt][nt][2], c[mt][nt][3]);
            if (r0 < nrows)
                *(uint32_t*)(g_h1h + (size_t)r0 * FF + col) = *(uint32_t*)&lo;
            if (r0 + 8 < nrows)
                *(uint32_t*)(g_h1h + (size_t)(r0 + 8) * FF + col) = *(uint32_t*)&hi;
        }
    }
}

// ---------------- CSR gather ----------------
// agg_i = dis_i^2*h1_i + sum_e coef_e * h1_{src_e}, then either:
//   do_pool=0: aggh_i = fp16(relu(agg_i + bias))
//   do_pool=1: mean-pool reduction of relu(agg_i + bias) into g_sums
// One warp per node; lane owns features [lane*4, lane*4+4) as fp16 pairs.
// Interleaved int2 {src, coef} metadata. 4-wide batches, named scalars,
// no predication (R10-R15 proven structure — do not restructure, see R14).

__device__ __forceinline__ void acc_h4(float4& acc, uint2 raw, float c) {
    float2 f0 = __half22float2(*(__half2*)&raw.x);
    float2 f1 = __half22float2(*(__half2*)&raw.y);
    acc.x = fmaf(c, f0.x, acc.x);
    acc.y = fmaf(c, f0.y, acc.y);
    acc.z = fmaf(c, f1.x, acc.z);
    acc.w = fmaf(c, f1.y, acc.w);
}

__global__ __launch_bounds__(256) void k_gather(
    const float* __restrict__ bias, const int* __restrict__ batch, int do_pool)
{
    int t = blockIdx.x * blockDim.x + threadIdx.x;
    int i = t >> 5, lane = t & 31;
    if (i >= NN) return;

    float di = g_dis[i];
    float cself = di * di;
    float4 acc = make_float4(0.f, 0.f, 0.f, 0.f);
    acc_h4(acc, *(const uint2*)(g_h1h + (size_t)i * FF + lane * 4), cself);

    int start = g_rowoff[i];
    int cnt   = g_deg[i] - 1;

    for (int j0 = 0; j0 < cnt; j0 += 32) {
        int myj = j0 + lane;
        int   s = 0;
        float c = 0.0f;
        if (myj < cnt) {
            int2 e = g_csr[start + myj];
            s = e.x;
            c = __int_as_float(e.y);
        }
        int m = min(32, cnt - j0);

        for (int u0 = 0; u0 < m; u0 += 4) {
            int   s0 = __shfl_sync(0xffffffffu, s, u0 + 0);
            int   s1 = __shfl_sync(0xffffffffu, s, u0 + 1);
            int   s2 = __shfl_sync(0xffffffffu, s, u0 + 2);
            int   s3 = __shfl_sync(0xffffffffu, s, u0 + 3);
            float w0 = __shfl_sync(0xffffffffu, c, u0 + 0);
            float w1 = __shfl_sync(0xffffffffu, c, u0 + 1);
            float w2 = __shfl_sync(0xffffffffu, c, u0 + 2);
            float w3 = __shfl_sync(0xffffffffu, c, u0 + 3);
            uint2 v0 = *(const uint2*)(g_h1h + (size_t)s0 * FF + lane * 4);
            uint2 v1 = *(const uint2*)(g_h1h + (size_t)s1 * FF + lane * 4);
            uint2 v2 = *(const uint2*)(g_h1h + (size_t)s2 * FF + lane * 4);
            uint2 v3 = *(const uint2*)(g_h1h + (size_t)s3 * FF + lane * 4);
            acc_h4(acc, v0, w0);
            acc_h4(acc, v1, w1);
            acc_h4(acc, v2, w2);
            acc_h4(acc, v3, w3);
        }
    }

    // bias + relu epilogue (shared by both paths; fp32 arithmetic)
    const float4 b = *(const float4*)(bias + lane * 4);
    float x = fmaxf(acc.x + b.x, 0.0f);
    float y = fmaxf(acc.y + b.y, 0.0f);
    float z = fmaxf(acc.z + b.z, 0.0f);
    float w = fmaxf(acc.w + b.w, 0.0f);

    if (do_pool) {
        int g = batch[i];
        red_add_v4(g_sums + (size_t)g * FF + lane * 4, x, y, z, w);
    } else {
        __half2 p0 = __floats2half2_rn(x, y);
        __half2 p1 = __floats2half2_rn(z, w);
        uint2 packed = make_uint2(*(uint32_t*)&p0, *(uint32_t*)&p1);
        *(uint2*)(g_aggh + (size_t)i * FF + lane * 4) = packed;
    }
}

// ---------------- head: out[g] = (sums[g]/cnt[g]) @ Wc + bc ----------------

__global__ void k_final(const float* __restrict__ Wc, const float* __restrict__ bc,
                        float* __restrict__ out) {
    __shared__ float r[CC][FF];
    int g = blockIdx.x;
    int t = threadIdx.x;  // 128 threads
    float p = g_sums[g * FF + t] / fmaxf(g_cnt[g], 1.0f);
    r[0][t] = p * Wc[t * CC + 0];
    r[1][t] = p * Wc[t * CC + 1];
    r[2][t] = p * Wc[t * CC + 2];
    __syncthreads();
    for (int s = 64; s > 0; s >>= 1) {
        if (t < s) {
            r[0][t] += r[0][t + s];
            r[1][t] += r[1][t + s];
            r[2][t] += r[2][t + s];
        }
        __syncthreads();
    }
    if (t < CC) out[g * CC + t] = r[t][0] + bc[t];
}

// ---------------- launch ----------------

extern "C" void kernel_launch(void* const* d_in, const int* in_sizes, int n_in,
                              void* d_out, int out_size) {
    const float* x     = (const float*)d_in[0];
    const int*   ei    = (const int*)d_in[1];   // [2, E] int32
    const int*   batch = (const int*)d_in[2];
    const float* W1    = (const float*)d_in[3];
    const float* b1    = (const float*)d_in[4];
    const float* W2    = (const float*)d_in[5];
    const float* b2    = (const float*)d_in[6];
    const float* W3    = (const float*)d_in[7];
    const float* b3    = (const float*)d_in[8];
    const float* Wc    = (const float*)d_in[9];
    const float* bc    = (const float*)d_in[10];
    float* out = (float*)d_out;

    const int* src = ei;
    const int* dst = ei + EE;

    cudaFuncSetAttribute(k_gemm, cudaFuncAttributeMaxDynamicSharedMemorySize, SM_BYTES);

    const int T = 256;
    int nb_n  = (NN + T - 1) / T;
    int nb_e4 = (EE / 4 + T - 1) / T;                // 4-edge-per-thread sweeps
    int nb_nw = ((size_t)NN * 32 + T - 1) / T;       // warp-per-node kernels
    int nb_g  = (NN + 127) / 128;                    // GEMM row blocks
    int nb_w  = (3 * FF * FF + T - 1) / T;

    // Stream-fork setup (R9 measured win): preproc chain is independent of
    // GEMM-1; fork it onto a side stream under capture, join before gather-1.
    static cudaStream_t s_side = nullptr;
    static cudaEvent_t  s_evFork = nullptr, s_evJoin = nullptr;
    if (s_side == nullptr) {
        cudaStreamCreateWithFlags(&s_side, cudaStreamNonBlocking);
        cudaEventCreateWithFlags(&s_evFork, cudaEventDisableTiming);
        cudaEventCreateWithFlags(&s_evJoin, cudaEventDisableTiming);
    }
    cudaStreamCaptureStatus cst = cudaStreamCaptureStatusNone;
    cudaStreamIsCapturing(cudaStreamPerThread, &cst);
    bool fork = (cst == cudaStreamCaptureStatusActive);

    cudaStream_t sm = fork ? cudaStreamPerThread : (cudaStream_t)0;  // main
    cudaStream_t sp = fork ? s_side : sm;                            // preproc

    if (fork) {
        cudaEventRecord(s_evFork, sm);
        cudaStreamWaitEvent(sp, s_evFork, 0);
    }

    // Graph preprocessing (side stream when forked)
    k_init<<<nb_n, T, 0, sp>>>();
    k_count<<<nb_e4, T, 0, sp>>>(dst);
    k_bsum<<<NSB, SB, 0, sp>>>(batch);     // fused: dis + cursor + graph counts + sums
    k_rowoff<<<NSB, SB, 0, sp>>>();        // fused inter-block scan + local scan
    k_bin<<<nb_e4, T, 0, sp>>>(src, dst);

    // Weight prep + Layer 1 GEMM (main stream, concurrent with preproc)
    k_wprep<<<nb_w, T, 0, sm>>>(W1, W2, W3);
    k_gemm<<<nb_g, T, SM_BYTES, sm>>>(x, 0, 0, NN);

    if (fork) {
        cudaEventRecord(s_evJoin, sp);
        cudaStreamWaitEvent(sm, s_evJoin, 0);
    }

    // Layer 1 aggregate; epilogue applies relu(.+b1), stores fp16 aggh
    k_gather<<<nb_nw, T, 0, sm>>>(b1, nullptr, 0);

    // Layer 2
    k_gemm<<<nb_g, T, SM_BYTES, sm>>>(nullptr, 1, 1, NN);
    k_gather<<<nb_nw, T, 0, sm>>>(b2, nullptr, 0);

    // Layer 3 (gather epilogue: relu(.+b3) + mean-pool reduction)
    k_gemm<<<nb_g, T, SM_BYTES, sm>>>(nullptr, 1, 2, NN);
    k_gather<<<nb_nw, T, 0, sm>>>(b3, batch, 1);

    // Classify
    k_final<<<GG, FF, 0, sm>>>(Wc, bc, out);
}

// round 17
// speedup vs baseline: 1.0109x; 1.0109x over previous
#include <cuda_runtime.h>
#include <cuda_fp16.h>
#include <cstdint>

// Problem constants (fixed by the dataset)
#define NN 100000
#define EE 1600000
#define FF 128
#define GG 64
#define CC 3

#define SB 1024
#define NSB ((NN + SB - 1) / SB)   // 98

// Scratch: __device__ globals (no allocation allowed)
__device__ int    g_deg[NN];
__device__ float  g_dis[NN];
__device__ __half g_h1h[(size_t)NN * FF];  // GEMM output (fp16; gather consumes)
__device__ __half g_aggh[(size_t)NN * FF]; // activated aggregation (fp16; GEMM consumes)
__device__ float  g_sums[GG * FF];
__device__ float  g_cnt[GG];
__device__ int    g_rowoff[NN];
__device__ int    g_cursor[NN];
__device__ int    g_bsum[NSB];
__device__ int2   g_csr[EE];               // interleaved {src, coef_bits}
// Pre-transposed, hi/lo-split weights: Wt[n][k] fp16 (W = Wh + Wl exactly-ish)
__device__ __align__(16) __half g_wt_h[3][FF * FF];
__device__ __align__(16) __half g_wt_l[3][FF * FF];

__device__ __forceinline__ void red_add_v4(float* addr, float x, float y, float z, float w) {
    asm volatile("red.global.add.v4.f32 [%0], {%1, %2, %3, %4};"
                 :: "l"(addr), "f"(x), "f"(y), "f"(z), "f"(w) : "memory");
}

__device__ __forceinline__ void mma16816(float* c, const uint32_t* a, uint32_t b0, uint32_t b1) {
    asm volatile(
        "mma.sync.aligned.m16n8k16.row.col.f32.f16.f16.f32 "
        "{%0,%1,%2,%3}, {%4,%5,%6,%7}, {%8,%9}, {%0,%1,%2,%3};\n"
        : "+f"(c[0]), "+f"(c[1]), "+f"(c[2]), "+f"(c[3])
        : "r"(a[0]), "r"(a[1]), "r"(a[2]), "r"(a[3]), "r"(b0), "r"(b1));
}

// ---------------- init / degree ----------------

__global__ void k_init() {
    int i = blockIdx.x * blockDim.x + threadIdx.x;
    if (i < NN) g_deg[i] = 1;             // self-loop
    if (i < GG * FF) g_sums[i] = 0.0f;
    if (i < GG) g_cnt[i] = 0.0f;
}

__global__ void k_count(const int* __restrict__ dst) {
    int e = blockIdx.x * blockDim.x + threadIdx.x;
    if (e < EE) atomicAdd(&g_deg[dst[e]], 1);
}

// ---------------- weight prep: Wt_h/Wt_l[n][k] = hi/lo fp16 split of W[k][n] ----------

__global__ void k_wprep(const float* __restrict__ W1, const float* __restrict__ W2,
                        const float* __restrict__ W3) {
    int idx = blockIdx.x * blockDim.x + threadIdx.x;
    if (idx >= 3 * FF * FF) return;
    int mat = idx / (FF * FF);
    int r   = idx % (FF * FF);
    int n = r / FF, k = r % FF;
    const float* W = (mat == 0) ? W1 : (mat == 1) ? W2 : W3;
    float w = W[k * FF + n];
    __half h = __float2half_rn(w);
    __half l = __float2half_rn(w - __half2float(h));
    g_wt_h[mat][n * FF + k] = h;
    g_wt_l[mat][n * FF + k] = l;
}

// ---------------- fused: dis/cursor/graph-count + per-block degree sums ----------------

__global__ __launch_bounds__(SB) void k_bsum(const int* __restrict__ batch) {
    __shared__ int sh[SB];
    int i = blockIdx.x * SB + threadIdx.x;
    int d = 0;
    if (i < NN) {
        d = g_deg[i];
        g_dis[i] = rsqrtf((float)d);
        g_cursor[i] = 0;
        atomicAdd(&g_cnt[batch[i]], 1.0f);
    }
    sh[threadIdx.x] = (i < NN) ? (d - 1) : 0;
    __syncthreads();
    for (int s = SB / 2; s > 0; s >>= 1) {
        if (threadIdx.x < s) sh[threadIdx.x] += sh[threadIdx.x + s];
        __syncthreads();
    }
    if (threadIdx.x == 0) g_bsum[blockIdx.x] = sh[0];
}

// rowoff with fused inter-block scan: each block computes its own base as a
// masked block-reduce over g_bsum (removes the separate scan launch).
__global__ __launch_bounds__(SB) void k_rowoff() {
    __shared__ int sh[SB];
    __shared__ int bs[128];
    int t = threadIdx.x;

    if (t < 128) bs[t] = (t < NSB && t < blockIdx.x) ? g_bsum[t] : 0;
    __syncthreads();
    for (int s = 64; s > 0; s >>= 1) {
        if (t < s) bs[t] += bs[t + s];
        __syncthreads();
    }
    int base = bs[0];

    int i = blockIdx.x * SB + t;
    int v = (i < NN) ? (g_deg[i] - 1) : 0;
    sh[t] = v;
    __syncthreads();
    for (int off = 1; off < SB; off <<= 1) {
        int u = (t >= off) ? sh[t - off] : 0;
        __syncthreads();
        sh[t] += u;
        __syncthreads();
    }
    if (i < NN)
        g_rowoff[i] = base + sh[t] - v;   // exclusive
}

__global__ void k_bin(const int* __restrict__ src, const int* __restrict__ dst) {
    int e = blockIdx.x * blockDim.x + threadIdx.x;
    if (e >= EE) return;
    int s = src[e], d = dst[e];
    int pos = atomicAdd(&g_cursor[d], 1);
    int idx = g_rowoff[d] + pos;
    float coef = g_dis[s] * g_dis[d];
    g_csr[idx] = make_int2(s, __float_as_int(coef));
}

// ---------------- HMMA GEMM: h1h = fp16( A @ W ) ----------------
// A is either external fp32 x (layer 1) or fp16 g_aggh (layers 2/3, bias+relu
// already applied by the gather epilogue). W pre-split hi/lo fp16, both resident
// in SMEM (single-pass mainloop — the R16 2-pass variant measured slower).
// mma.sync.m16n8k16, 8 warps in 4x2 grid, fp32 accumulators, padded SMEM.

#define APAD 136
#define SM_A  0                      // halves offsets
#define SM_BH (128 * APAD)
#define SM_BL (256 * APAD)
#define SM_HALVES (384 * APAD)
#define SM_BYTES (SM_HALVES * 2)     // 104448

__global__ __launch_bounds__(256) void k_gemm(
    const float* __restrict__ Aext, int useAgg, int wmat, int nrows)
{
    extern __shared__ __half sh[];
    int block_row = blockIdx.x * 128;
    int tid = threadIdx.x;

    // ---- load A tile into SMEM as fp16 ----
    if (useAgg) {
        // direct fp16 copy from g_aggh (already activated)
#pragma unroll
        for (int it = 0; it < 8; it++) {
            int q = tid + it * 256;      // 2048 uint4
            int row = q >> 4;
            int col = (q & 15) * 8;
            int grow = block_row + row;
            uint4 v = make_uint4(0u, 0u, 0u, 0u);
            if (grow < nrows) v = *(const uint4*)(g_aggh + (size_t)grow * FF + col);
            *(uint4*)(sh + SM_A + row * APAD + col) = v;
        }
    } else {
        // fp32 external x -> fp16 convert
#pragma unroll
        for (int it = 0; it < 16; it++) {
            int q = tid + it * 256;      // 4096 float4
            int row = q >> 5;
            int col = (q & 31) * 4;
            int grow = block_row + row;
            float4 av = make_float4(0.f, 0.f, 0.f, 0.f);
            if (grow < nrows) av = *(const float4*)(Aext + (size_t)grow * FF + col);
            __half2 p0 = __floats2half2_rn(av.x, av.y);
            __half2 p1 = __floats2half2_rn(av.z, av.w);
            uint2 packed = make_uint2(*(uint32_t*)&p0, *(uint32_t*)&p1);
            *(uint2*)(sh + SM_A + row * APAD + col) = packed;
        }
    }

    // ---- copy Wt hi/lo (each 128x128 fp16) into padded SMEM ----
    {
        const uint4* wh = (const uint4*)&g_wt_h[wmat][0];
        const uint4* wl = (const uint4*)&g_wt_l[wmat][0];
#pragma unroll
        for (int it = 0; it < 8; it++) {
            int q = tid + it * 256;      // 2048 uint4 per matrix
            int n = q >> 4;              // 16 uint4 per 128-half row
            int k = (q & 15) * 8;
            *(uint4*)(sh + SM_BH + n * APAD + k) = wh[q];
            *(uint4*)(sh + SM_BL + n * APAD + k) = wl[q];
        }
    }
    __syncthreads();

    // ---- mma mainloop ----
    int wid = tid >> 5, lane = tid & 31;
    int wm = wid >> 1, wn = wid & 1;     // 4x2 warp grid: 32 rows x 64 cols each
    int g = lane >> 2, t4 = lane & 3;

    float c[2][8][4];
#pragma unroll
    for (int mt = 0; mt < 2; mt++)
#pragma unroll
        for (int nt = 0; nt < 8; nt++)
#pragma unroll
            for (int r = 0; r < 4; r++) c[mt][nt][r] = 0.0f;

    for (int ks = 0; ks < 8; ks++) {
        int kb = ks * 16;
        uint32_t a[2][4];
#pragma unroll
        for (int mt = 0; mt < 2; mt++) {
            const __half* ab = sh + SM_A + (wm * 32 + mt * 16 + g) * APAD + kb + 2 * t4;
            a[mt][0] = *(const uint32_t*)(ab);
            a[mt][1] = *(const uint32_t*)(ab + 8 * APAD);
            a[mt][2] = *(const uint32_t*)(ab + 8);
            a[mt][3] = *(const uint32_t*)(ab + 8 * APAD + 8);
        }
#pragma unroll
        for (int nt = 0; nt < 8; nt++) {
            int coff = (wn * 64 + nt * 8 + g) * APAD + kb + 2 * t4;
            uint32_t bh0 = *(const uint32_t*)(sh + SM_BH + coff);
            uint32_t bh1 = *(const uint32_t*)(sh + SM_BH + coff + 8);
            uint32_t bl0 = *(const uint32_t*)(sh + SM_BL + coff);
            uint32_t bl1 = *(const uint32_t*)(sh + SM_BL + coff + 8);
            mma16816(c[0][nt], a[0], bh0, bh1);
            mma16816(c[0][nt], a[0], bl0, bl1);
            mma16816(c[1][nt], a[1], bh0, bh1);
            mma16816(c[1][nt], a[1], bl0, bl1);
        }
    }

    // ---- epilogue: fp16 store ----
#pragma unroll
    for (int mt = 0; mt < 2; mt++) {
        int r0 = block_row + wm * 32 + mt * 16 + g;
#pragma unroll
        for (int nt = 0; nt < 8; nt++) {
            int col = wn * 64 + nt * 8 + 2 * t4;
            __half2 lo = __floats2half2_rn(c[mt][nt][0], c[mt][nt][1]);
            __half2 hi = __floats2half2_rn(c[mt][nt][2], c[mt][nt][3]);
            if (r0 < nrows)
                *(uint32_t*)(g_h1h + (size_t)r0 * FF + col) = *(uint32_t*)&lo;
            if (r0 + 8 < nrows)
                *(uint32_t*)(g_h1h + (size_t)(r0 + 8) * FF + col) = *(uint32_t*)&hi;
        }
    }
}

// ---------------- CSR gather ----------------
// agg_i = dis_i^2*h1_i + sum_e coef_e * h1_{src_e}, then either:
//   do_pool=0: aggh_i = fp16(relu(agg_i + bias))
//   do_pool=1: mean-pool reduction of relu(agg_i + bias) into g_sums
// One warp per node; lane owns features [lane*4, lane*4+4) as fp16 pairs.
// Interleaved int2 {src, coef} metadata (ONE LDG.64 per lane-edge).
// 4-wide batches, named scalars, no predication (R10-R15 proven — do not
// restructure; two-nodes-per-warp and deep staging both measured slower).

__device__ __forceinline__ void acc_h4(float4& acc, uint2 raw, float c) {
    float2 f0 = __half22float2(*(__half2*)&raw.x);
    float2 f1 = __half22float2(*(__half2*)&raw.y);
    acc.x = fmaf(c, f0.x, acc.x);
    acc.y = fmaf(c, f0.y, acc.y);
    acc.z = fmaf(c, f1.x, acc.z);
    acc.w = fmaf(c, f1.y, acc.w);
}

__global__ __launch_bounds__(256) void k_gather(
    const float* __restrict__ bias, const int* __restrict__ batch, int do_pool)
{
    int t = blockIdx.x * blockDim.x + threadIdx.x;
    int i = t >> 5, lane = t & 31;
    if (i >= NN) return;

    float di = g_dis[i];
    float cself = di * di;
    float4 acc = make_float4(0.f, 0.f, 0.f, 0.f);
    acc_h4(acc, *(const uint2*)(g_h1h + (size_t)i * FF + lane * 4), cself);

    int start = g_rowoff[i];
    int cnt   = g_deg[i] - 1;

    for (int j0 = 0; j0 < cnt; j0 += 32) {
        int myj = j0 + lane;
        int   s = 0;
        float c = 0.0f;
        if (myj < cnt) {
            int2 e = g_csr[start + myj];
            s = e.x;
            c = __int_as_float(e.y);
        }
        int m = min(32, cnt - j0);

        for (int u0 = 0; u0 < m; u0 += 4) {
            int   s0 = __shfl_sync(0xffffffffu, s, u0 + 0);
            int   s1 = __shfl_sync(0xffffffffu, s, u0 + 1);
            int   s2 = __shfl_sync(0xffffffffu, s, u0 + 2);
            int   s3 = __shfl_sync(0xffffffffu, s, u0 + 3);
            float w0 = __shfl_sync(0xffffffffu, c, u0 + 0);
            float w1 = __shfl_sync(0xffffffffu, c, u0 + 1);
            float w2 = __shfl_sync(0xffffffffu, c, u0 + 2);
            float w3 = __shfl_sync(0xffffffffu, c, u0 + 3);
            uint2 v0 = *(const uint2*)(g_h1h + (size_t)s0 * FF + lane * 4);
            uint2 v1 = *(const uint2*)(g_h1h + (size_t)s1 * FF + lane * 4);
            uint2 v2 = *(const uint2*)(g_h1h + (size_t)s2 * FF + lane * 4);
            uint2 v3 = *(const uint2*)(g_h1h + (size_t)s3 * FF + lane * 4);
            acc_h4(acc, v0, w0);
            acc_h4(acc, v1, w1);
            acc_h4(acc, v2, w2);
            acc_h4(acc, v3, w3);
        }
    }

    // bias + relu epilogue (shared by both paths; fp32 arithmetic)
    const float4 b = *(const float4*)(bias + lane * 4);
    float x = fmaxf(acc.x + b.x, 0.0f);
    float y = fmaxf(acc.y + b.y, 0.0f);
    float z = fmaxf(acc.z + b.z, 0.0f);
    float w = fmaxf(acc.w + b.w, 0.0f);

    if (do_pool) {
        int g = batch[i];
        red_add_v4(g_sums + (size_t)g * FF + lane * 4, x, y, z, w);
    } else {
        __half2 p0 = __floats2half2_rn(x, y);
        __half2 p1 = __floats2half2_rn(z, w);
        uint2 packed = make_uint2(*(uint32_t*)&p0, *(uint32_t*)&p1);
        *(uint2*)(g_aggh + (size_t)i * FF + lane * 4) = packed;
    }
}

// ---------------- head: out[g] = (sums[g]/cnt[g]) @ Wc + bc ----------------

__global__ void k_final(const float* __restrict__ Wc, const float* __restrict__ bc,
                        float* __restrict__ out) {
    __shared__ float r[CC][FF];
    int g = blockIdx.x;
    int t = threadIdx.x;  // 128 threads
    float p = g_sums[g * FF + t] / fmaxf(g_cnt[g], 1.0f);
    r[0][t] = p * Wc[t * CC + 0];
    r[1][t] = p * Wc[t * CC + 1];
    r[2][t] = p * Wc[t * CC + 2];
    __syncthreads();
    for (int s = 64; s > 0; s >>= 1) {
        if (t < s) {
            r[0][t] += r[0][t + s];
            r[1][t] += r[1][t + s];
            r[2][t] += r[2][t + s];
        }
        __syncthreads();
    }
    if (t < CC) out[g * CC + t] = r[t][0] + bc[t];
}

// ---------------- launch ----------------

extern "C" void kernel_launch(void* const* d_in, const int* in_sizes, int n_in,
                              void* d_out, int out_size) {
    const float* x     = (const float*)d_in[0];
    const int*   ei    = (const int*)d_in[1];   // [2, E] int32
    const int*   batch = (const int*)d_in[2];
    const float* W1    = (const float*)d_in[3];
    const float* b1    = (const float*)d_in[4];
    const float* W2    = (const float*)d_in[5];
    const float* b2    = (const float*)d_in[6];
    const float* W3    = (const float*)d_in[7];
    const float* b3    = (const float*)d_in[8];
    const float* Wc    = (const float*)d_in[9];
    const float* bc    = (const float*)d_in[10];
    float* out = (float*)d_out;

    const int* src = ei;
    const int* dst = ei + EE;

    cudaFuncSetAttribute(k_gemm, cudaFuncAttributeMaxDynamicSharedMemorySize, SM_BYTES);

    const int T = 256;
    int nb_n  = (NN + T - 1) / T;
    int nb_e  = (EE + T - 1) / T;
    int nb_nw = ((size_t)NN * 32 + T - 1) / T;       // warp-per-node kernels
    int nb_g  = (NN + 127) / 128;                    // GEMM row blocks
    int nb_w  = (3 * FF * FF + T - 1) / T;

    // Stream-fork setup (R9 measured win): preproc chain is independent of
    // GEMM-1; fork it onto a side stream under capture, join before gather-1.
    static cudaStream_t s_side = nullptr;
    static cudaEvent_t  s_evFork = nullptr, s_evJoin = nullptr;
    if (s_side == nullptr) {
        cudaStreamCreateWithFlags(&s_side, cudaStreamNonBlocking);
        cudaEventCreateWithFlags(&s_evFork, cudaEventDisableTiming);
        cudaEventCreateWithFlags(&s_evJoin, cudaEventDisableTiming);
    }
    cudaStreamCaptureStatus cst = cudaStreamCaptureStatusNone;
    cudaStreamIsCapturing(cudaStreamPerThread, &cst);
    bool fork = (cst == cudaStreamCaptureStatusActive);

    cudaStream_t sm = fork ? cudaStreamPerThread : (cudaStream_t)0;  // main
    cudaStream_t sp = fork ? s_side : sm;                            // preproc

    if (fork) {
        cudaEventRecord(s_evFork, sm);
        cudaStreamWaitEvent(sp, s_evFork, 0);
    }

    // Graph preprocessing (side stream when forked)
    k_init<<<nb_n, T, 0, sp>>>();
    k_count<<<nb_e, T, 0, sp>>>(dst);
    k_bsum<<<NSB, SB, 0, sp>>>(batch);     // fused: dis + cursor + graph counts + sums
    k_rowoff<<<NSB, SB, 0, sp>>>();        // fused inter-block scan + local scan
    k_bin<<<nb_e, T, 0, sp>>>(src, dst);

    // Weight prep + Layer 1 GEMM (main stream, concurrent with preproc)
    k_wprep<<<nb_w, T, 0, sm>>>(W1, W2, W3);
    k_gemm<<<nb_g, T, SM_BYTES, sm>>>(x, 0, 0, NN);

    if (fork) {
        cudaEventRecord(s_evJoin, sp);
        cudaStreamWaitEvent(sm, s_evJoin, 0);
    }

    // Layer 1 aggregate; epilogue applies relu(.+b1), stores fp16 aggh
    k_gather<<<nb_nw, T, 0, sm>>>(b1, nullptr, 0);

    // Layer 2
    k_gemm<<<nb_g, T, SM_BYTES, sm>>>(nullptr, 1, 1, NN);
    k_gather<<<nb_nw, T, 0, sm>>>(b2, nullptr, 0);

    // Layer 3 (gather epilogue: relu(.+b3) + mean-pool reduction)
    k_gemm<<<nb_g, T, SM_BYTES, sm>>>(nullptr, 1, 2, NN);
    k_gather<<<nb_nw, T, 0, sm>>>(b3, batch, 1);

    // Classify
    k_final<<<GG, FF, 0, sm>>>(Wc, bc, out);
}